// round 5
// baseline (speedup 1.0000x reference)
#include <cuda_runtime.h>
#include <math.h>

#define NN   20000
#define EE   320000
#define BBATCH 128
#define FIN  25
#define DIM  64
#define NH   8
#define F512 512   // NH*DIM
#define S2S_CAP 768   // max cached rows per graph segment (768*64*4 = 196608 B)

// ---------------- scratch (static device globals; no allocation) ----------------
__device__ float g_h0[NN * DIM];
__device__ float g_xh[NN * F512];
__device__ float g_as[NN * NH];
__device__ float g_ad[NN * NH];
__device__ int   g_cnt[NN];
__device__ int   g_offs[NN + 1];
__device__ int   g_cursor[NN];
__device__ int   g_csr[EE];
__device__ float g_agg[NN * F512];
__device__ float g_out[NN * DIM];

__device__ __forceinline__ float lrelu(float x) { return x > 0.f ? x : 0.2f * x; }
__device__ __forceinline__ float sigmoidf_(float x) { return 1.f / (1.f + __expf(-x)); }

// ---------------- k1: h0 = relu(x @ W0 + b0) ----------------
__global__ void k_h0(const float* __restrict__ x, const float* __restrict__ W0,
                     const float* __restrict__ b0) {
    __shared__ float sW[FIN * DIM];
    __shared__ float sb[DIM];
    __shared__ float sx[4][FIN];
    int tid = threadIdx.x;
    for (int i = tid; i < FIN * DIM; i += 256) sW[i] = W0[i];
    if (tid < DIM) sb[tid] = b0[tid];
    int rb = blockIdx.x * 4;
    if (tid < 4 * FIN) sx[tid / FIN][tid % FIN] = x[rb * FIN + tid];
    __syncthreads();
    int c = tid & 63, r = tid >> 6;
    float acc = sb[c];
#pragma unroll
    for (int k = 0; k < FIN; k++) acc = fmaf(sx[r][k], sW[k * DIM + c], acc);
    g_h0[(rb + r) * DIM + c] = fmaxf(acc, 0.f);
}

// ---------------- k2: xh = h0 @ Wg  (N x 64 @ 64 x 512) ----------------
__global__ void __launch_bounds__(256) k_xh(const float* __restrict__ Wg) {
    __shared__ float h0s[32][65];
    int tid = threadIdx.x;
    int rb = blockIdx.x * 32;
    for (int idx = tid; idx < 32 * DIM; idx += 256)
        h0s[idx >> 6][idx & 63] = g_h0[rb * DIM + idx];
    __syncthreads();
    int tc = tid & 63, tr = tid >> 6;
    float acc[8][8];
#pragma unroll
    for (int i = 0; i < 8; i++)
#pragma unroll
        for (int j = 0; j < 8; j++) acc[i][j] = 0.f;
#pragma unroll 4
    for (int k = 0; k < DIM; k++) {
        float wv[8];
#pragma unroll
        for (int j = 0; j < 8; j++) wv[j] = __ldg(&Wg[k * F512 + tc + 64 * j]);
#pragma unroll
        for (int i = 0; i < 8; i++) {
            float hv = h0s[tr * 8 + i][k];
#pragma unroll
            for (int j = 0; j < 8; j++) acc[i][j] = fmaf(hv, wv[j], acc[i][j]);
        }
    }
#pragma unroll
    for (int i = 0; i < 8; i++) {
        size_t row = (size_t)(rb + tr * 8 + i) * F512;
#pragma unroll
        for (int j = 0; j < 8; j++) g_xh[row + tc + 64 * j] = acc[i][j];
    }
}

// ---------------- k2b: a_s, a_d — one WARP per node, coalesced float4 ----------
__global__ void k_att(const float* __restrict__ att_src, const float* __restrict__ att_dst) {
    int n = (blockIdx.x * blockDim.x + threadIdx.x) >> 5;
    int lane = threadIdx.x & 31;
    if (n >= NN) return;
    const float4* row = (const float4*)(g_xh + (size_t)n * F512);
    int a = lane >> 4;          // 0 or 1
    int b = lane & 15;          // channel-group within head
    float ps[4], pd[4];
#pragma unroll
    for (int j = 0; j < 4; j++) {
        int f = lane + 32 * j;          // float4 index; head h = 2j + a, chan4 = b
        int h = 2 * j + a;
        float4 v = row[f];
        float4 as4 = __ldg((const float4*)&att_src[h * 64 + 4 * b]);
        float4 ad4 = __ldg((const float4*)&att_dst[h * 64 + 4 * b]);
        ps[j] = v.x * as4.x + v.y * as4.y + v.z * as4.z + v.w * as4.w;
        pd[j] = v.x * ad4.x + v.y * ad4.y + v.z * ad4.z + v.w * ad4.w;
    }
#pragma unroll
    for (int o = 8; o; o >>= 1) {
#pragma unroll
        for (int j = 0; j < 4; j++) {
            ps[j] += __shfl_xor_sync(0xffffffffu, ps[j], o);
            pd[j] += __shfl_xor_sync(0xffffffffu, pd[j], o);
        }
    }
    if (b == 0) {
#pragma unroll
        for (int j = 0; j < 4; j++) {
            g_as[n * 8 + 2 * j + a] = ps[j];
            g_ad[n * 8 + 2 * j + a] = pd[j];
        }
    }
}

// ---------------- CSR build ----------------
__global__ void k_zero() {
    int i = blockIdx.x * 256 + threadIdx.x;
    if (i < NN) g_cnt[i] = 0;
}
__global__ void k_hist(const int* __restrict__ ei) {
    int e = blockIdx.x * 256 + threadIdx.x;
    if (e < EE) atomicAdd(&g_cnt[ei[EE + e]], 1);
}
__global__ void k_scan() {  // 1 block, 1024 threads
    __shared__ int partials[1024];
    int t = threadIdx.x;
    const int CH = 20;
    int base = t * CH;
    int local[CH];
    int s = 0;
#pragma unroll
    for (int u = 0; u < CH; u++) {
        int idx = base + u;
        int v = (idx < NN) ? g_cnt[idx] : 0;
        local[u] = s;
        s += v;
    }
    partials[t] = s;
    __syncthreads();
    for (int o = 1; o < 1024; o <<= 1) {
        int v = (t >= o) ? partials[t - o] : 0;
        __syncthreads();
        partials[t] += v;
        __syncthreads();
    }
    int pre = (t > 0) ? partials[t - 1] : 0;
#pragma unroll
    for (int u = 0; u < CH; u++) {
        int idx = base + u;
        if (idx < NN) {
            int o = pre + local[u];
            g_offs[idx] = o;
            g_cursor[idx] = o;
        }
    }
    if (t == 1023) g_offs[NN] = partials[1023];
}
__global__ void k_scatter(const int* __restrict__ ei) {
    int e = blockIdx.x * 256 + threadIdx.x;
    if (e < EE) {
        int d = ei[EE + e];
        int p = atomicAdd(&g_cursor[d], 1);
        g_csr[p] = ei[e];
    }
}

// ---------------- k4: GAT aggregation, warp per dst node, 4-edge batched ------
__global__ void __launch_bounds__(256) k_agg(const float* __restrict__ bg) {
    int n = (blockIdx.x * blockDim.x + threadIdx.x) >> 5;
    int lane = threadIdx.x & 31;
    if (n >= NN) return;
    int s0 = g_offs[n], s1 = g_offs[n + 1];
    int eh = lane & 7;                 // head for w-lane
    int eslot = lane >> 3;             // edge slot 0..3 for w-lane
    float adh = g_ad[n * 8 + eh];

    // ---- pass 1: per-head max (4 edges/iter + prefetch) ----
    float m = -INFINITY;
    if (lane < 8) m = lrelu(g_as[n * 8 + lane] + adh);   // self-loop
    {
        int i = s0 + (lane >> 3);
        int src = (i < s1) ? g_csr[i] : -1;
        while (i < s1) {
            int inext = i + 4;
            int srcn = (inext < s1) ? g_csr[inext] : -1;
            float e = lrelu(g_as[src * 8 + eh] + adh);
            m = fmaxf(m, e);
            src = srcn;
            i = inext;
        }
    }
    m = fmaxf(m, __shfl_xor_sync(0xffffffffu, m, 8));
    m = fmaxf(m, __shfl_xor_sync(0xffffffffu, m, 16));
    // every lane now holds max for head (lane & 7)

    // ---- pass 2: weighted accumulate, 4 edges per iteration ----
    // edge t: src = (t==0) ? n : csr[s0+t-1];  total = cnt+1
    int total = (s1 - s0) + 1;
    float4 acc[4];
#pragma unroll
    for (int j = 0; j < 4; j++) acc[j] = make_float4(0.f, 0.f, 0.f, 0.f);
    float ssum = 0.f;

    // prefetch srcs for first group (lanes 0..3 meaningful, all lanes compute)
    int myt = (lane & 3);
    int s = n;
    if (myt > 0 && myt < total) s = g_csr[s0 + myt - 1];

    for (int t0 = 0; t0 < total; t0 += 4) {
        int scur = s;
        // prefetch next group
        int mytn = t0 + 4 + (lane & 3);
        s = n;
        if (mytn < total) s = g_csr[s0 + mytn - 1];

        // per-lane attention weight for (edge eslot, head eh)
        int esrc = __shfl_sync(0xffffffffu, scur, eslot);
        float w = 0.f;
        if (t0 + eslot < total) {
            float e = lrelu(g_as[esrc * 8 + eh] + adh);
            w = __expf(e - m);
        }
        ssum += w;

#pragma unroll
        for (int r = 0; r < 4; r++) {
            int sr = __shfl_sync(0xffffffffu, scur, r);
            const float4* row = (const float4*)(g_xh + (size_t)sr * F512);
#pragma unroll
            for (int j = 0; j < 4; j++) {
                int f = lane + 32 * j;
                float wj = __shfl_sync(0xffffffffu, w, r * 8 + (f >> 4));
                float4 v = row[f];
                acc[j].x = fmaf(wj, v.x, acc[j].x);
                acc[j].y = fmaf(wj, v.y, acc[j].y);
                acc[j].z = fmaf(wj, v.z, acc[j].z);
                acc[j].w = fmaf(wj, v.w, acc[j].w);
            }
        }
    }
    // reduce ssum over edge slots -> per-head sum in every lane with head lane&7
    ssum += __shfl_xor_sync(0xffffffffu, ssum, 8);
    ssum += __shfl_xor_sync(0xffffffffu, ssum, 16);

    float4* orow = (float4*)(g_agg + (size_t)n * F512);
#pragma unroll
    for (int j = 0; j < 4; j++) {
        int f = lane + 32 * j;
        float sj = __shfl_sync(0xffffffffu, ssum, f >> 4);
        float inv = 1.0f / sj;
        int ch = 4 * f;
        float4 bgv = __ldg((const float4*)&bg[ch]);
        float4 o;
        o.x = fmaxf(acc[j].x * inv + bgv.x, 0.f);
        o.y = fmaxf(acc[j].y * inv + bgv.y, 0.f);
        o.z = fmaxf(acc[j].z * inv + bgv.z, 0.f);
        o.w = fmaxf(acc[j].w * inv + bgv.w, 0.f);
        orow[f] = o;
    }
}

// ---------------- k5: out = relu(agg @ Wh + bh)  (N x 512 @ 512 x 64) ----------
__global__ void __launch_bounds__(256) k_out(const float* __restrict__ Wh,
                                             const float* __restrict__ bh) {
    __shared__ float As[128][33];
    __shared__ float Bs[32][68];
    int tid = threadIdx.x;
    int rb = blockIdx.x * 128;
    int c0 = (tid & 15) * 4, r0 = (tid >> 4) * 8;
    float acc[8][4];
#pragma unroll
    for (int i = 0; i < 8; i++)
#pragma unroll
        for (int j = 0; j < 4; j++) acc[i][j] = 0.f;
    for (int kc = 0; kc < F512; kc += 32) {
        for (int idx = tid; idx < 128 * 32; idx += 256) {
            int r = idx >> 5, k = idx & 31;
            int row = rb + r;
            As[r][k] = (row < NN) ? g_agg[(size_t)row * F512 + kc + k] : 0.f;
        }
        for (int idx = tid; idx < 32 * 64; idx += 256) {
            int k = idx >> 6, c = idx & 63;
            Bs[k][c] = Wh[(kc + k) * 64 + c];
        }
        __syncthreads();
#pragma unroll 8
        for (int k = 0; k < 32; k++) {
            float4 bv = *(const float4*)&Bs[k][c0];
#pragma unroll
            for (int i = 0; i < 8; i++) {
                float av = As[r0 + i][k];
                acc[i][0] = fmaf(av, bv.x, acc[i][0]);
                acc[i][1] = fmaf(av, bv.y, acc[i][1]);
                acc[i][2] = fmaf(av, bv.z, acc[i][2]);
                acc[i][3] = fmaf(av, bv.w, acc[i][3]);
            }
        }
        __syncthreads();
    }
    float4 bh4 = *(const float4*)&bh[c0];
#pragma unroll
    for (int i = 0; i < 8; i++) {
        int row = rb + r0 + i;
        if (row < NN) {
            float4 o;
            o.x = fmaxf(acc[i][0] + bh4.x, 0.f);
            o.y = fmaxf(acc[i][1] + bh4.y, 0.f);
            o.z = fmaxf(acc[i][2] + bh4.z, 0.f);
            o.w = fmaxf(acc[i][3] + bh4.w, 0.f);
            *(float4*)&g_out[(size_t)row * 64 + c0] = o;
        }
    }
}

// ---------------- k6: Set2Set (3 steps) + final MLP; one block per graph -------
// graph's node rows cached in dynamic smem (fits: avg ~156 rows, cap 768)
__global__ void __launch_bounds__(256) k_s2s(
    const int* __restrict__ batch, const float* __restrict__ W_ih,
    const float* __restrict__ W_hh, const float* __restrict__ b_ih,
    const float* __restrict__ b_hh, const float* __restrict__ W1,
    const float* __restrict__ b1, const float* __restrict__ W2,
    const float* __restrict__ b2, float* __restrict__ y) {
    extern __shared__ float sout[];   // up to S2S_CAP rows x 64
    int b = blockIdx.x;
    int tid = threadIdx.x, lane = tid & 31, wid = tid >> 5;
    __shared__ float qs[128], hhv[64], ccv[64], gg[256];
    __shared__ float red[8][64];
    __shared__ float sred[8], mw[8];
    __shared__ float mfin_s;
    __shared__ int seg[2];
    if (tid == 0) {
        int lo = 0, hi = NN;
        while (lo < hi) { int mid = (lo + hi) >> 1; if (batch[mid] < b) lo = mid + 1; else hi = mid; }
        seg[0] = lo;
        hi = NN;
        while (lo < hi) { int mid = (lo + hi) >> 1; if (batch[mid] < b + 1) lo = mid + 1; else hi = mid; }
        seg[1] = lo;
    }
    if (tid < 128) qs[tid] = 0.f;
    if (tid < 64) { hhv[tid] = 0.f; ccv[tid] = 0.f; }
    __syncthreads();
    int s0 = seg[0], s1 = seg[1];
    int cnt = s1 - s0;
    bool fits = (cnt <= S2S_CAP);
    if (fits) {
        for (int idx = tid; idx < cnt * 64; idx += 256)
            sout[idx] = g_out[(size_t)s0 * 64 + idx];
    }
    __syncthreads();

    for (int it = 0; it < 3; ++it) {
        // LSTM cell
        float g = b_ih[tid] + b_hh[tid];
        const float* wi = W_ih + tid * 128;
#pragma unroll 4
        for (int k = 0; k < 128; k++) g = fmaf(qs[k], wi[k], g);
        const float* wh = W_hh + tid * 64;
#pragma unroll 4
        for (int k = 0; k < 64; k++) g = fmaf(hhv[k], wh[k], g);
        gg[tid] = g;
        __syncthreads();
        if (tid < 64) {
            float ig = gg[tid], fg = gg[64 + tid], gv = gg[128 + tid], og = gg[192 + tid];
            float c = sigmoidf_(fg) * ccv[tid] + sigmoidf_(ig) * tanhf(gv);
            ccv[tid] = c;
            hhv[tid] = sigmoidf_(og) * tanhf(c);
        }
        __syncthreads();

        float q0 = hhv[lane], q1 = hhv[lane + 32];
        float wmax = -INFINITY;
        for (int i = wid; i < cnt; i += 8) {
            const float* o = fits ? (sout + i * 64) : (g_out + (size_t)(s0 + i) * 64);
            float v = o[lane] * q0 + o[lane + 32] * q1;
#pragma unroll
            for (int off = 16; off; off >>= 1) v += __shfl_xor_sync(0xffffffffu, v, off);
            wmax = fmaxf(wmax, v);
        }
        if (lane == 0) mw[wid] = wmax;
        __syncthreads();
        if (tid == 0) {
            float m = -INFINITY;
#pragma unroll
            for (int w = 0; w < 8; w++) m = fmaxf(m, mw[w]);
            mfin_s = m;
        }
        __syncthreads();
        float m = mfin_s;
        float r0a = 0.f, r1a = 0.f, sl = 0.f;
        for (int i = wid; i < cnt; i += 8) {
            const float* o = fits ? (sout + i * 64) : (g_out + (size_t)(s0 + i) * 64);
            float a0 = o[lane], a1 = o[lane + 32];
            float v = a0 * q0 + a1 * q1;
#pragma unroll
            for (int off = 16; off; off >>= 1) v += __shfl_xor_sync(0xffffffffu, v, off);
            float w = __expf(v - m);
            sl += w;
            r0a = fmaf(w, a0, r0a);
            r1a = fmaf(w, a1, r1a);
        }
        red[wid][lane] = r0a;
        red[wid][lane + 32] = r1a;
        if (lane == 0) sred[wid] = sl;
        __syncthreads();
        if (tid < 64) {
            float s = 0.f, r = 0.f;
#pragma unroll
            for (int w = 0; w < 8; w++) { s += sred[w]; r += red[w][tid]; }
            float inv = (s > 0.f) ? 1.0f / s : 0.f;
            qs[tid] = hhv[tid];
            qs[64 + tid] = r * inv;
        }
        __syncthreads();
    }

    if (tid < 64) {
        float z = b1[tid];
#pragma unroll 4
        for (int k = 0; k < 128; k++) z = fmaf(qs[k], W1[k * 64 + tid], z);
        gg[tid] = fmaxf(z, 0.f);
    }
    __syncthreads();
    if (tid < 32) {
        float p = gg[tid] * W2[tid] + gg[tid + 32] * W2[tid + 32];
#pragma unroll
        for (int off = 16; off; off >>= 1) p += __shfl_xor_sync(0xffffffffu, p, off);
        if (tid == 0) y[b] = p + b2[0];
    }
}

// ---------------- launch ----------------
extern "C" void kernel_launch(void* const* d_in, const int* in_sizes, int n_in,
                              void* d_out, int out_size) {
    const float* x       = (const float*)d_in[0];
    const int*   ei      = (const int*)d_in[1];   // [2,E] int32
    const int*   batch   = (const int*)d_in[2];
    const float* W0      = (const float*)d_in[3];
    const float* b0      = (const float*)d_in[4];
    const float* Wg      = (const float*)d_in[5];
    const float* att_src = (const float*)d_in[6];
    const float* att_dst = (const float*)d_in[7];
    const float* bg      = (const float*)d_in[8];
    const float* Wh      = (const float*)d_in[9];
    const float* bh      = (const float*)d_in[10];
    const float* W_ih    = (const float*)d_in[11];
    const float* W_hh    = (const float*)d_in[12];
    const float* b_ih    = (const float*)d_in[13];
    const float* b_hh    = (const float*)d_in[14];
    const float* W1      = (const float*)d_in[15];
    const float* b1      = (const float*)d_in[16];
    const float* W2      = (const float*)d_in[17];
    const float* b2      = (const float*)d_in[18];
    float* y = (float*)d_out;

    static cudaStream_t s_side = nullptr;
    static cudaEvent_t evFork = nullptr, evJoin = nullptr;
    static bool s_init = false;
    if (!s_init) {
        cudaStreamCreateWithFlags(&s_side, cudaStreamNonBlocking);
        cudaEventCreateWithFlags(&evFork, cudaEventDisableTiming);
        cudaEventCreateWithFlags(&evJoin, cudaEventDisableTiming);
        cudaFuncSetAttribute(k_s2s, cudaFuncAttributeMaxDynamicSharedMemorySize,
                             S2S_CAP * 64 * sizeof(float));
        s_init = true;
    }

    bool overlap = (s_side != nullptr && evFork != nullptr && evJoin != nullptr);
    cudaStream_t side = overlap ? s_side : (cudaStream_t)0;

    if (overlap) {
        cudaEventRecord(evFork, 0);
        cudaStreamWaitEvent(side, evFork, 0);
    }
    // CSR chain (independent of x-path) on side stream
    k_zero<<<(NN + 255) / 256, 256, 0, side>>>();
    k_hist<<<(EE + 255) / 256, 256, 0, side>>>(ei);
    k_scan<<<1, 1024, 0, side>>>();
    k_scatter<<<(EE + 255) / 256, 256, 0, side>>>(ei);
    if (overlap) cudaEventRecord(evJoin, side);

    // x path on main stream
    k_h0<<<NN / 4, 256>>>(x, W0, b0);
    k_xh<<<NN / 32, 256>>>(Wg);
    k_att<<<(NN * 32 + 255) / 256, 256>>>(att_src, att_dst);

    if (overlap) cudaStreamWaitEvent(0, evJoin, 0);
    k_agg<<<NN / 8, 256>>>(bg);
    k_out<<<(NN + 127) / 128, 256>>>(Wh, bh);
    k_s2s<<<BBATCH, 256, S2S_CAP * 64 * sizeof(float)>>>(batch, W_ih, W_hh, b_ih, b_hh,
                                                         W1, b1, W2, b2, y);
}

// round 6
// speedup vs baseline: 1.3218x; 1.3218x over previous
#include <cuda_runtime.h>
#include <math.h>

#define NN   20000
#define EE   320000
#define BBATCH 128
#define FIN  25
#define DIM  64
#define NH   8
#define F512 512   // NH*DIM

// ---------------- scratch (static device globals; no allocation) ----------------
__device__ float g_h0[NN * DIM];
__device__ float g_xh[NN * F512];
__device__ float g_as[NN * NH];
__device__ float g_ad[NN * NH];
__device__ int   g_cnt[NN];
__device__ int   g_offs[NN + 1];
__device__ int   g_cursor[NN];
__device__ int   g_csr[EE];
__device__ float g_agg[NN * F512];
__device__ float g_out[NN * DIM];

__device__ __forceinline__ float lrelu(float x) { return x > 0.f ? x : 0.2f * x; }
__device__ __forceinline__ float sigmoidf_(float x) { return 1.f / (1.f + __expf(-x)); }

// ---------------- k1: h0 = relu(x @ W0 + b0) ----------------
// block = 256 threads = 4 rows x 64 cols
__global__ void k_h0(const float* __restrict__ x, const float* __restrict__ W0,
                     const float* __restrict__ b0) {
    __shared__ float sW[FIN * DIM];
    __shared__ float sb[DIM];
    __shared__ float sx[4][FIN];
    int tid = threadIdx.x;
    for (int i = tid; i < FIN * DIM; i += 256) sW[i] = W0[i];
    if (tid < DIM) sb[tid] = b0[tid];
    int rb = blockIdx.x * 4;
    if (tid < 4 * FIN) sx[tid / FIN][tid % FIN] = x[rb * FIN + tid];
    __syncthreads();
    int c = tid & 63, r = tid >> 6;
    float acc = sb[c];
#pragma unroll
    for (int k = 0; k < FIN; k++) acc = fmaf(sx[r][k], sW[k * DIM + c], acc);
    g_h0[(rb + r) * DIM + c] = fmaxf(acc, 0.f);
}

// ---------------- k2: xh = h0 @ Wg  (N x 64 @ 64 x 512) ----------------
__global__ void __launch_bounds__(256) k_xh(const float* __restrict__ Wg) {
    __shared__ float h0s[32][65];
    int tid = threadIdx.x;
    int rb = blockIdx.x * 32;
    for (int idx = tid; idx < 32 * DIM; idx += 256)
        h0s[idx >> 6][idx & 63] = g_h0[rb * DIM + idx];
    __syncthreads();
    int tc = tid & 63, tr = tid >> 6;
    float acc[8][8];
#pragma unroll
    for (int i = 0; i < 8; i++)
#pragma unroll
        for (int j = 0; j < 8; j++) acc[i][j] = 0.f;
#pragma unroll 4
    for (int k = 0; k < DIM; k++) {
        float wv[8];
#pragma unroll
        for (int j = 0; j < 8; j++) wv[j] = __ldg(&Wg[k * F512 + tc + 64 * j]);
#pragma unroll
        for (int i = 0; i < 8; i++) {
            float hv = h0s[tr * 8 + i][k];
#pragma unroll
            for (int j = 0; j < 8; j++) acc[i][j] = fmaf(hv, wv[j], acc[i][j]);
        }
    }
#pragma unroll
    for (int i = 0; i < 8; i++) {
        size_t row = (size_t)(rb + tr * 8 + i) * F512;
#pragma unroll
        for (int j = 0; j < 8; j++) g_xh[row + tc + 64 * j] = acc[i][j];
    }
}

// ---------------- k2b: a_s, a_d — one WARP per node, coalesced float4 ----------
__global__ void k_att(const float* __restrict__ att_src, const float* __restrict__ att_dst) {
    int n = (blockIdx.x * blockDim.x + threadIdx.x) >> 5;
    int lane = threadIdx.x & 31;
    if (n >= NN) return;
    const float4* row = (const float4*)(g_xh + (size_t)n * F512);
    int a = lane >> 4;          // 0 or 1
    int b = lane & 15;          // channel-group within head
    float ps[4], pd[4];
#pragma unroll
    for (int j = 0; j < 4; j++) {
        int f = lane + 32 * j;          // float4 index; head h = 2j + a, chan4 = b
        int h = 2 * j + a;
        float4 v = row[f];
        float4 as4 = __ldg((const float4*)&att_src[h * 64 + 4 * b]);
        float4 ad4 = __ldg((const float4*)&att_dst[h * 64 + 4 * b]);
        ps[j] = v.x * as4.x + v.y * as4.y + v.z * as4.z + v.w * as4.w;
        pd[j] = v.x * ad4.x + v.y * ad4.y + v.z * ad4.z + v.w * ad4.w;
    }
#pragma unroll
    for (int o = 8; o; o >>= 1) {
#pragma unroll
        for (int j = 0; j < 4; j++) {
            ps[j] += __shfl_xor_sync(0xffffffffu, ps[j], o);
            pd[j] += __shfl_xor_sync(0xffffffffu, pd[j], o);
        }
    }
    if (b == 0) {
#pragma unroll
        for (int j = 0; j < 4; j++) {
            g_as[n * 8 + 2 * j + a] = ps[j];
            g_ad[n * 8 + 2 * j + a] = pd[j];
        }
    }
}

// ---------------- CSR build ----------------
__global__ void k_zero() {
    int i = blockIdx.x * 256 + threadIdx.x;
    if (i < NN) g_cnt[i] = 0;
}
__global__ void k_hist(const int* __restrict__ ei) {
    int e = blockIdx.x * 256 + threadIdx.x;
    if (e < EE) atomicAdd(&g_cnt[ei[EE + e]], 1);
}
__global__ void k_scan() {  // 1 block, 1024 threads
    __shared__ int partials[1024];
    int t = threadIdx.x;
    const int CH = 20;  // 1024*20 = 20480 >= NN
    int base = t * CH;
    int local[CH];
    int s = 0;
#pragma unroll
    for (int u = 0; u < CH; u++) {
        int idx = base + u;
        int v = (idx < NN) ? g_cnt[idx] : 0;
        local[u] = s;
        s += v;
    }
    partials[t] = s;
    __syncthreads();
    for (int o = 1; o < 1024; o <<= 1) {
        int v = (t >= o) ? partials[t - o] : 0;
        __syncthreads();
        partials[t] += v;
        __syncthreads();
    }
    int pre = (t > 0) ? partials[t - 1] : 0;
#pragma unroll
    for (int u = 0; u < CH; u++) {
        int idx = base + u;
        if (idx < NN) {
            int o = pre + local[u];
            g_offs[idx] = o;
            g_cursor[idx] = o;
        }
    }
    if (t == 1023) g_offs[NN] = partials[1023];
}
__global__ void k_scatter(const int* __restrict__ ei) {
    int e = blockIdx.x * 256 + threadIdx.x;
    if (e < EE) {
        int d = ei[EE + e];
        int p = atomicAdd(&g_cursor[d], 1);
        g_csr[p] = ei[e];
    }
}

// ---------------- k4: GAT aggregation, warp per dst node ----------------
// pass1: per-head max of leaky_relu(a_s[src]+a_d[n]) (4 edges x 8 heads per iter)
// pass2: w = exp(e - m); acc += w * xh[src]; then agg = relu(acc/sum + bg)
// (R1 structure + next-edge prefetch in pass 2 to break csr->row load dependency)
__global__ void __launch_bounds__(256) k_agg(const float* __restrict__ bg) {
    int n = (blockIdx.x * blockDim.x + threadIdx.x) >> 5;
    int lane = threadIdx.x & 31;
    if (n >= NN) return;
    int s0 = g_offs[n], s1 = g_offs[n + 1];
    int hh = lane & 7;
    float adh = g_ad[n * 8 + hh];

    // ---- pass 1: max ----
    float m = -INFINITY;
    if (lane < 8) m = lrelu(g_as[n * 8 + lane] + adh);  // self-loop
    for (int i = s0 + (lane >> 3); i < s1; i += 4) {
        int src = g_csr[i];
        float e = lrelu(g_as[src * 8 + hh] + adh);
        m = fmaxf(m, e);
    }
    m = fmaxf(m, __shfl_xor_sync(0xffffffffu, m, 8));
    m = fmaxf(m, __shfl_xor_sync(0xffffffffu, m, 16));
    // lane l holds max for head (l&7)

    // ---- pass 2: weighted accumulate (prefetched) ----
    float4 acc[4];
#pragma unroll
    for (int j = 0; j < 4; j++) acc[j] = make_float4(0.f, 0.f, 0.f, 0.f);
    float ssum = 0.f;
    int src_cur = n;                              // first edge: self-loop
    for (int i = s0 - 1; i < s1; ++i) {
        int inext = i + 1;
        int src_next = (inext < s1) ? g_csr[inext] : 0;   // prefetch next csr entry
        float w = 0.f;
        if (lane < 8) {
            float e = lrelu(g_as[src_cur * 8 + lane] + adh);
            w = __expf(e - m);
            ssum += w;
        }
        const float4* row = (const float4*)(g_xh + (size_t)src_cur * F512);
#pragma unroll
        for (int j = 0; j < 4; j++) {
            int f = lane + 32 * j;
            float wj = __shfl_sync(0xffffffffu, w, f >> 4);
            float4 v = row[f];
            acc[j].x = fmaf(wj, v.x, acc[j].x);
            acc[j].y = fmaf(wj, v.y, acc[j].y);
            acc[j].z = fmaf(wj, v.z, acc[j].z);
            acc[j].w = fmaf(wj, v.w, acc[j].w);
        }
        src_cur = src_next;
    }
    float4* orow = (float4*)(g_agg + (size_t)n * F512);
#pragma unroll
    for (int j = 0; j < 4; j++) {
        int f = lane + 32 * j;
        float sj = __shfl_sync(0xffffffffu, ssum, f >> 4);
        float inv = 1.0f / sj;
        int ch = 4 * f;
        float4 bgv = __ldg((const float4*)&bg[ch]);
        float4 o;
        o.x = fmaxf(acc[j].x * inv + bgv.x, 0.f);
        o.y = fmaxf(acc[j].y * inv + bgv.y, 0.f);
        o.z = fmaxf(acc[j].z * inv + bgv.z, 0.f);
        o.w = fmaxf(acc[j].w * inv + bgv.w, 0.f);
        orow[f] = o;
    }
}

// ---------------- k5: out = relu(agg @ Wh + bh)  (N x 512 @ 512 x 64) ----------
__global__ void __launch_bounds__(256) k_out(const float* __restrict__ Wh,
                                             const float* __restrict__ bh) {
    __shared__ float As[128][33];
    __shared__ float Bs[32][68];
    int tid = threadIdx.x;
    int rb = blockIdx.x * 128;
    int c0 = (tid & 15) * 4, r0 = (tid >> 4) * 8;
    float acc[8][4];
#pragma unroll
    for (int i = 0; i < 8; i++)
#pragma unroll
        for (int j = 0; j < 4; j++) acc[i][j] = 0.f;
    for (int kc = 0; kc < F512; kc += 32) {
        for (int idx = tid; idx < 128 * 32; idx += 256) {
            int r = idx >> 5, k = idx & 31;
            int row = rb + r;
            As[r][k] = (row < NN) ? g_agg[(size_t)row * F512 + kc + k] : 0.f;
        }
        for (int idx = tid; idx < 32 * 64; idx += 256) {
            int k = idx >> 6, c = idx & 63;
            Bs[k][c] = Wh[(kc + k) * 64 + c];
        }
        __syncthreads();
#pragma unroll 8
        for (int k = 0; k < 32; k++) {
            float4 bv = *(const float4*)&Bs[k][c0];
#pragma unroll
            for (int i = 0; i < 8; i++) {
                float av = As[r0 + i][k];
                acc[i][0] = fmaf(av, bv.x, acc[i][0]);
                acc[i][1] = fmaf(av, bv.y, acc[i][1]);
                acc[i][2] = fmaf(av, bv.z, acc[i][2]);
                acc[i][3] = fmaf(av, bv.w, acc[i][3]);
            }
        }
        __syncthreads();
    }
    float4 bh4 = *(const float4*)&bh[c0];
#pragma unroll
    for (int i = 0; i < 8; i++) {
        int row = rb + r0 + i;
        if (row < NN) {
            float4 o;
            o.x = fmaxf(acc[i][0] + bh4.x, 0.f);
            o.y = fmaxf(acc[i][1] + bh4.y, 0.f);
            o.z = fmaxf(acc[i][2] + bh4.z, 0.f);
            o.w = fmaxf(acc[i][3] + bh4.w, 0.f);
            *(float4*)&g_out[(size_t)row * 64 + c0] = o;
        }
    }
}

// ---------------- k6: Set2Set (3 steps) + final MLP; one block per graph -------
__global__ void __launch_bounds__(256) k_s2s(
    const int* __restrict__ batch, const float* __restrict__ W_ih,
    const float* __restrict__ W_hh, const float* __restrict__ b_ih,
    const float* __restrict__ b_hh, const float* __restrict__ W1,
    const float* __restrict__ b1, const float* __restrict__ W2,
    const float* __restrict__ b2, float* __restrict__ y) {
    int b = blockIdx.x;
    int tid = threadIdx.x, lane = tid & 31, wid = tid >> 5;
    __shared__ float qs[128], hhv[64], ccv[64], gg[256];
    __shared__ float red[8][64];
    __shared__ float sred[8], mw[8];
    __shared__ float mfin_s;
    __shared__ int seg[2];
    if (tid == 0) {
        int lo = 0, hi = NN;
        while (lo < hi) { int mid = (lo + hi) >> 1; if (batch[mid] < b) lo = mid + 1; else hi = mid; }
        seg[0] = lo;
        hi = NN;
        while (lo < hi) { int mid = (lo + hi) >> 1; if (batch[mid] < b + 1) lo = mid + 1; else hi = mid; }
        seg[1] = lo;
    }
    if (tid < 128) qs[tid] = 0.f;
    if (tid < 64) { hhv[tid] = 0.f; ccv[tid] = 0.f; }
    __syncthreads();
    int s0 = seg[0], s1 = seg[1];

    for (int it = 0; it < 3; ++it) {
        // LSTM cell (per-graph row)
        float g = b_ih[tid] + b_hh[tid];
        const float* wi = W_ih + tid * 128;
#pragma unroll 4
        for (int k = 0; k < 128; k++) g = fmaf(qs[k], wi[k], g);
        const float* wh = W_hh + tid * 64;
#pragma unroll 4
        for (int k = 0; k < 64; k++) g = fmaf(hhv[k], wh[k], g);
        gg[tid] = g;
        __syncthreads();
        if (tid < 64) {
            float ig = gg[tid], fg = gg[64 + tid], gv = gg[128 + tid], og = gg[192 + tid];
            float c = sigmoidf_(fg) * ccv[tid] + sigmoidf_(ig) * tanhf(gv);
            ccv[tid] = c;
            hhv[tid] = sigmoidf_(og) * tanhf(c);
        }
        __syncthreads();

        // attention over this graph's nodes, q = hhv
        float q0 = hhv[lane], q1 = hhv[lane + 32];
        float wmax = -INFINITY;
        for (int i = s0 + wid; i < s1; i += 8) {
            const float* o = g_out + (size_t)i * 64;
            float v = o[lane] * q0 + o[lane + 32] * q1;
#pragma unroll
            for (int off = 16; off; off >>= 1) v += __shfl_xor_sync(0xffffffffu, v, off);
            wmax = fmaxf(wmax, v);
        }
        if (lane == 0) mw[wid] = wmax;
        __syncthreads();
        if (tid == 0) {
            float m = -INFINITY;
#pragma unroll
            for (int w = 0; w < 8; w++) m = fmaxf(m, mw[w]);
            mfin_s = m;
        }
        __syncthreads();
        float m = mfin_s;
        float r0a = 0.f, r1a = 0.f, sl = 0.f;
        for (int i = s0 + wid; i < s1; i += 8) {
            const float* o = g_out + (size_t)i * 64;
            float a0 = o[lane], a1 = o[lane + 32];
            float v = a0 * q0 + a1 * q1;
#pragma unroll
            for (int off = 16; off; off >>= 1) v += __shfl_xor_sync(0xffffffffu, v, off);
            float w = __expf(v - m);
            sl += w;
            r0a = fmaf(w, a0, r0a);
            r1a = fmaf(w, a1, r1a);
        }
        red[wid][lane] = r0a;
        red[wid][lane + 32] = r1a;
        if (lane == 0) sred[wid] = sl;
        __syncthreads();
        if (tid < 64) {
            float s = 0.f, r = 0.f;
#pragma unroll
            for (int w = 0; w < 8; w++) { s += sred[w]; r += red[w][tid]; }
            float inv = (s > 0.f) ? 1.0f / s : 0.f;
            qs[tid] = hhv[tid];
            qs[64 + tid] = r * inv;
        }
        __syncthreads();
    }

    // final MLP: y = relu(q_star @ W1 + b1) @ W2 + b2
    if (tid < 64) {
        float z = b1[tid];
#pragma unroll 4
        for (int k = 0; k < 128; k++) z = fmaf(qs[k], W1[k * 64 + tid], z);
        gg[tid] = fmaxf(z, 0.f);
    }
    __syncthreads();
    if (tid < 32) {
        float p = gg[tid] * W2[tid] + gg[tid + 32] * W2[tid + 32];
#pragma unroll
        for (int off = 16; off; off >>= 1) p += __shfl_xor_sync(0xffffffffu, p, off);
        if (tid == 0) y[b] = p + b2[0];
    }
}

// ---------------- launch (single stream, R1 ordering) ----------------
extern "C" void kernel_launch(void* const* d_in, const int* in_sizes, int n_in,
                              void* d_out, int out_size) {
    const float* x       = (const float*)d_in[0];
    const int*   ei      = (const int*)d_in[1];   // [2,E] int32
    const int*   batch   = (const int*)d_in[2];
    const float* W0      = (const float*)d_in[3];
    const float* b0      = (const float*)d_in[4];
    const float* Wg      = (const float*)d_in[5];
    const float* att_src = (const float*)d_in[6];
    const float* att_dst = (const float*)d_in[7];
    const float* bg      = (const float*)d_in[8];
    const float* Wh      = (const float*)d_in[9];
    const float* bh      = (const float*)d_in[10];
    const float* W_ih    = (const float*)d_in[11];
    const float* W_hh    = (const float*)d_in[12];
    const float* b_ih    = (const float*)d_in[13];
    const float* b_hh    = (const float*)d_in[14];
    const float* W1      = (const float*)d_in[15];
    const float* b1      = (const float*)d_in[16];
    const float* W2      = (const float*)d_in[17];
    const float* b2      = (const float*)d_in[18];
    float* y = (float*)d_out;

    k_h0<<<NN / 4, 256>>>(x, W0, b0);
    k_xh<<<NN / 32, 256>>>(Wg);
    k_att<<<(NN * 32 + 255) / 256, 256>>>(att_src, att_dst);
    k_zero<<<(NN + 255) / 256, 256>>>();
    k_hist<<<(EE + 255) / 256, 256>>>(ei);
    k_scan<<<1, 1024>>>();
    k_scatter<<<(EE + 255) / 256, 256>>>(ei);
    k_agg<<<NN / 8, 256>>>(bg);
    k_out<<<(NN + 127) / 128, 256>>>(Wh, bh);
    k_s2s<<<BBATCH, 256>>>(batch, W_ih, W_hh, b_ih, b_hh, W1, b1, W2, b2, y);
}

// round 7
// speedup vs baseline: 1.4293x; 1.0813x over previous
#include <cuda_runtime.h>
#include <cuda_fp16.h>
#include <math.h>

#define NN   20000
#define EE   320000
#define BBATCH 128
#define FIN  25
#define DIM  64
#define NH   8
#define F512 512   // NH*DIM

// ---------------- scratch (static device globals; no allocation) ----------------
__device__ float   g_h0[NN * DIM];
__device__ __half2 g_xh2[NN * (F512 / 2)];   // xh in fp16, half2-packed (20.5MB)
__device__ float   g_P[DIM * 16];            // folded att projections [k][o], o<8 src, o>=8 dst
__device__ float   g_as[NN * NH];
__device__ float   g_ad[NN * NH];
__device__ int     g_cnt[NN];
__device__ int     g_offs[NN + 1];
__device__ int     g_cursor[NN];
__device__ int     g_csr[EE];
__device__ float   g_agg[NN * F512];
__device__ float   g_out[NN * DIM];

__device__ __forceinline__ float lrelu(float x) { return x > 0.f ? x : 0.2f * x; }
__device__ __forceinline__ float sigmoidf_(float x) { return 1.f / (1.f + __expf(-x)); }

// ---------------- k1: h0 = relu(x @ W0 + b0) ----------------
__global__ void k_h0(const float* __restrict__ x, const float* __restrict__ W0,
                     const float* __restrict__ b0) {
    __shared__ float sW[FIN * DIM];
    __shared__ float sb[DIM];
    __shared__ float sx[4][FIN];
    int tid = threadIdx.x;
    for (int i = tid; i < FIN * DIM; i += 256) sW[i] = W0[i];
    if (tid < DIM) sb[tid] = b0[tid];
    int rb = blockIdx.x * 4;
    if (tid < 4 * FIN) sx[tid / FIN][tid % FIN] = x[rb * FIN + tid];
    __syncthreads();
    int c = tid & 63, r = tid >> 6;
    float acc = sb[c];
#pragma unroll
    for (int k = 0; k < FIN; k++) acc = fmaf(sx[r][k], sW[k * DIM + c], acc);
    g_h0[(rb + r) * DIM + c] = fmaxf(acc, 0.f);
}

// ---------------- k_patt: P[k][o] = sum_c Wg[k, 64h+c]*att[h,c]  (1 block) ------
__global__ void k_patt(const float* __restrict__ Wg, const float* __restrict__ as_,
                       const float* __restrict__ ad_) {
    int k = threadIdx.x >> 4, o = threadIdx.x & 15;  // 1024 threads = 64 x 16
    int h = o & 7;
    const float* att = (o < 8) ? as_ : ad_;
    float s = 0.f;
#pragma unroll 8
    for (int c = 0; c < 64; c++)
        s = fmaf(Wg[k * F512 + h * 64 + c], att[h * 64 + c], s);
    g_P[k * 16 + o] = s;
}

// ---------------- k_att2: a_s/a_d = h0 @ P  (full fp32, exact) ------------------
__global__ void k_att2() {
    int idx = blockIdx.x * 256 + threadIdx.x;
    int n = idx >> 4, o = idx & 15;
    if (n >= NN) return;
    const float* h0r = g_h0 + (size_t)n * DIM;
    float s = 0.f;
#pragma unroll 8
    for (int k = 0; k < DIM; k++) s = fmaf(h0r[k], g_P[k * 16 + o], s);
    if (o < 8) g_as[n * 8 + o] = s;
    else       g_ad[n * 8 + (o - 8)] = s;
}

// ---------------- k2: xh = h0 @ Wg  (N x 64 @ 64 x 512), fp16 out ---------------
// 256 threads: tr=tid>>5 -> 4 rows (tr*4..+3), tc2=tid&31 -> col pair 2*tc2 per head
__global__ void __launch_bounds__(256) k_xh(const float* __restrict__ Wg) {
    __shared__ float h0s[32][65];
    int tid = threadIdx.x;
    int rb = blockIdx.x * 32;
    for (int idx = tid; idx < 32 * DIM; idx += 256)
        h0s[idx >> 6][idx & 63] = g_h0[(size_t)rb * DIM + idx];
    __syncthreads();
    int tc2 = tid & 31, tr = tid >> 5;
    float2 acc[4][8];
#pragma unroll
    for (int i = 0; i < 4; i++)
#pragma unroll
        for (int j = 0; j < 8; j++) acc[i][j] = make_float2(0.f, 0.f);
#pragma unroll 4
    for (int k = 0; k < DIM; k++) {
        float2 wv[8];
#pragma unroll
        for (int j = 0; j < 8; j++)
            wv[j] = __ldg((const float2*)&Wg[k * F512 + 64 * j + 2 * tc2]);
#pragma unroll
        for (int i = 0; i < 4; i++) {
            float hv = h0s[tr * 4 + i][k];
#pragma unroll
            for (int j = 0; j < 8; j++) {
                acc[i][j].x = fmaf(hv, wv[j].x, acc[i][j].x);
                acc[i][j].y = fmaf(hv, wv[j].y, acc[i][j].y);
            }
        }
    }
#pragma unroll
    for (int i = 0; i < 4; i++) {
        size_t rowoff = (size_t)(rb + tr * 4 + i) * (F512 / 2);
#pragma unroll
        for (int j = 0; j < 8; j++)
            g_xh2[rowoff + 32 * j + tc2] = __floats2half2_rn(acc[i][j].x, acc[i][j].y);
    }
}

// ---------------- CSR build ----------------
__global__ void k_zero() {
    int i = blockIdx.x * 256 + threadIdx.x;
    if (i < NN) g_cnt[i] = 0;
}
__global__ void k_hist(const int* __restrict__ ei) {
    int e = blockIdx.x * 256 + threadIdx.x;
    if (e < EE) atomicAdd(&g_cnt[ei[EE + e]], 1);
}
__global__ void k_scan() {  // 1 block, 1024 threads
    __shared__ int partials[1024];
    int t = threadIdx.x;
    const int CH = 20;
    int base = t * CH;
    int local[CH];
    int s = 0;
#pragma unroll
    for (int u = 0; u < CH; u++) {
        int idx = base + u;
        int v = (idx < NN) ? g_cnt[idx] : 0;
        local[u] = s;
        s += v;
    }
    partials[t] = s;
    __syncthreads();
    for (int o = 1; o < 1024; o <<= 1) {
        int v = (t >= o) ? partials[t - o] : 0;
        __syncthreads();
        partials[t] += v;
        __syncthreads();
    }
    int pre = (t > 0) ? partials[t - 1] : 0;
#pragma unroll
    for (int u = 0; u < CH; u++) {
        int idx = base + u;
        if (idx < NN) {
            int o = pre + local[u];
            g_offs[idx] = o;
            g_cursor[idx] = o;
        }
    }
    if (t == 1023) g_offs[NN] = partials[1023];
}
__global__ void k_scatter(const int* __restrict__ ei) {
    int e = blockIdx.x * 256 + threadIdx.x;
    if (e < EE) {
        int d = ei[EE + e];
        int p = atomicAdd(&g_cursor[d], 1);
        g_csr[p] = ei[e];
    }
}

// ---------------- k4: GAT aggregation, warp per dst node (fp16 xh gather) -------
__global__ void __launch_bounds__(256) k_agg(const float* __restrict__ bg) {
    int n = (blockIdx.x * blockDim.x + threadIdx.x) >> 5;
    int lane = threadIdx.x & 31;
    if (n >= NN) return;
    int s0 = g_offs[n], s1 = g_offs[n + 1];
    int hh = lane & 7;
    float adh = g_ad[n * 8 + hh];

    // ---- pass 1: per-head max (4 edges/iter, prefetched) ----
    float m = -INFINITY;
    if (lane < 8) m = lrelu(g_as[n * 8 + lane] + adh);  // self-loop
    {
        int i = s0 + (lane >> 3);
        int src = (i < s1) ? g_csr[i] : -1;
        while (i < s1) {
            int inext = i + 4;
            int srcn = (inext < s1) ? g_csr[inext] : -1;
            float e = lrelu(g_as[src * 8 + hh] + adh);
            m = fmaxf(m, e);
            src = srcn;
            i = inext;
        }
    }
    m = fmaxf(m, __shfl_xor_sync(0xffffffffu, m, 8));
    m = fmaxf(m, __shfl_xor_sync(0xffffffffu, m, 16));
    // lane l holds max for head (l&7)

    // ---- pass 2: weighted accumulate ----
    // lane holds channels 8f..8f+7 for f = lane and f = lane+32 (int4 granules)
    float acc0[8], acc1[8];
#pragma unroll
    for (int t = 0; t < 8; t++) { acc0[t] = 0.f; acc1[t] = 0.f; }
    float ssum = 0.f;
    int head0 = lane >> 3;            // head of f=lane
    int head1 = (lane + 32) >> 3;     // head of f=lane+32
    int src_cur = n;                  // first edge: self-loop
    for (int i = s0 - 1; i < s1; ++i) {
        int inext = i + 1;
        int src_next = (inext < s1) ? g_csr[inext] : 0;
        const int4* row = (const int4*)(g_xh2 + (size_t)src_cur * (F512 / 2));
        int4 v0 = row[lane];
        int4 v1 = row[lane + 32];
        float w = 0.f;
        if (lane < 8) {
            float e = lrelu(g_as[src_cur * 8 + lane] + adh);
            w = __expf(e - m);
            ssum += w;
        }
        float wj0 = __shfl_sync(0xffffffffu, w, head0);
        float wj1 = __shfl_sync(0xffffffffu, w, head1);
        const __half2* hp0 = (const __half2*)&v0;
        const __half2* hp1 = (const __half2*)&v1;
#pragma unroll
        for (int t = 0; t < 4; t++) {
            float2 f0 = __half22float2(hp0[t]);
            float2 f1 = __half22float2(hp1[t]);
            acc0[2 * t]     = fmaf(wj0, f0.x, acc0[2 * t]);
            acc0[2 * t + 1] = fmaf(wj0, f0.y, acc0[2 * t + 1]);
            acc1[2 * t]     = fmaf(wj1, f1.x, acc1[2 * t]);
            acc1[2 * t + 1] = fmaf(wj1, f1.y, acc1[2 * t + 1]);
        }
        src_cur = src_next;
    }

    float sj0 = __shfl_sync(0xffffffffu, ssum, head0);
    float sj1 = __shfl_sync(0xffffffffu, ssum, head1);
    float inv0 = 1.0f / sj0, inv1 = 1.0f / sj1;
    float* orow = g_agg + (size_t)n * F512;
    {
        int ch = 8 * lane;
        float4 b0 = __ldg((const float4*)&bg[ch]);
        float4 b1 = __ldg((const float4*)&bg[ch + 4]);
        float4 o1, o2;
        o1.x = fmaxf(acc0[0] * inv0 + b0.x, 0.f);
        o1.y = fmaxf(acc0[1] * inv0 + b0.y, 0.f);
        o1.z = fmaxf(acc0[2] * inv0 + b0.z, 0.f);
        o1.w = fmaxf(acc0[3] * inv0 + b0.w, 0.f);
        o2.x = fmaxf(acc0[4] * inv0 + b1.x, 0.f);
        o2.y = fmaxf(acc0[5] * inv0 + b1.y, 0.f);
        o2.z = fmaxf(acc0[6] * inv0 + b1.z, 0.f);
        o2.w = fmaxf(acc0[7] * inv0 + b1.w, 0.f);
        *(float4*)&orow[ch] = o1;
        *(float4*)&orow[ch + 4] = o2;
    }
    {
        int ch = 8 * (lane + 32);
        float4 b0 = __ldg((const float4*)&bg[ch]);
        float4 b1 = __ldg((const float4*)&bg[ch + 4]);
        float4 o1, o2;
        o1.x = fmaxf(acc1[0] * inv1 + b0.x, 0.f);
        o1.y = fmaxf(acc1[1] * inv1 + b0.y, 0.f);
        o1.z = fmaxf(acc1[2] * inv1 + b0.z, 0.f);
        o1.w = fmaxf(acc1[3] * inv1 + b0.w, 0.f);
        o2.x = fmaxf(acc1[4] * inv1 + b1.x, 0.f);
        o2.y = fmaxf(acc1[5] * inv1 + b1.y, 0.f);
        o2.z = fmaxf(acc1[6] * inv1 + b1.z, 0.f);
        o2.w = fmaxf(acc1[7] * inv1 + b1.w, 0.f);
        *(float4*)&orow[ch] = o1;
        *(float4*)&orow[ch + 4] = o2;
    }
}

// ---------------- k5: out = relu(agg @ Wh + bh)  (N x 512 @ 512 x 64) ----------
__global__ void __launch_bounds__(256) k_out(const float* __restrict__ Wh,
                                             const float* __restrict__ bh) {
    __shared__ float As[128][33];
    __shared__ float Bs[32][68];
    int tid = threadIdx.x;
    int rb = blockIdx.x * 128;
    int c0 = (tid & 15) * 4, r0 = (tid >> 4) * 8;
    float acc[8][4];
#pragma unroll
    for (int i = 0; i < 8; i++)
#pragma unroll
        for (int j = 0; j < 4; j++) acc[i][j] = 0.f;
    for (int kc = 0; kc < F512; kc += 32) {
        for (int idx = tid; idx < 128 * 32; idx += 256) {
            int r = idx >> 5, k = idx & 31;
            int row = rb + r;
            As[r][k] = (row < NN) ? g_agg[(size_t)row * F512 + kc + k] : 0.f;
        }
        for (int idx = tid; idx < 32 * 64; idx += 256) {
            int k = idx >> 6, c = idx & 63;
            Bs[k][c] = Wh[(kc + k) * 64 + c];
        }
        __syncthreads();
#pragma unroll 8
        for (int k = 0; k < 32; k++) {
            float4 bv = *(const float4*)&Bs[k][c0];
#pragma unroll
            for (int i = 0; i < 8; i++) {
                float av = As[r0 + i][k];
                acc[i][0] = fmaf(av, bv.x, acc[i][0]);
                acc[i][1] = fmaf(av, bv.y, acc[i][1]);
                acc[i][2] = fmaf(av, bv.z, acc[i][2]);
                acc[i][3] = fmaf(av, bv.w, acc[i][3]);
            }
        }
        __syncthreads();
    }
    float4 bh4 = *(const float4*)&bh[c0];
#pragma unroll
    for (int i = 0; i < 8; i++) {
        int row = rb + r0 + i;
        if (row < NN) {
            float4 o;
            o.x = fmaxf(acc[i][0] + bh4.x, 0.f);
            o.y = fmaxf(acc[i][1] + bh4.y, 0.f);
            o.z = fmaxf(acc[i][2] + bh4.z, 0.f);
            o.w = fmaxf(acc[i][3] + bh4.w, 0.f);
            *(float4*)&g_out[(size_t)row * 64 + c0] = o;
        }
    }
}

// ---------------- k6: Set2Set (3 steps) + final MLP; one block per graph -------
__global__ void __launch_bounds__(256) k_s2s(
    const int* __restrict__ batch, const float* __restrict__ W_ih,
    const float* __restrict__ W_hh, const float* __restrict__ b_ih,
    const float* __restrict__ b_hh, const float* __restrict__ W1,
    const float* __restrict__ b1, const float* __restrict__ W2,
    const float* __restrict__ b2, float* __restrict__ y) {
    int b = blockIdx.x;
    int tid = threadIdx.x, lane = tid & 31, wid = tid >> 5;
    __shared__ float qs[128], hhv[64], ccv[64], gg[256];
    __shared__ float red[8][64];
    __shared__ float sred[8], mw[8];
    __shared__ float mfin_s;
    __shared__ int seg[2];
    if (tid == 0) {
        int lo = 0, hi = NN;
        while (lo < hi) { int mid = (lo + hi) >> 1; if (batch[mid] < b) lo = mid + 1; else hi = mid; }
        seg[0] = lo;
        hi = NN;
        while (lo < hi) { int mid = (lo + hi) >> 1; if (batch[mid] < b + 1) lo = mid + 1; else hi = mid; }
        seg[1] = lo;
    }
    if (tid < 128) qs[tid] = 0.f;
    if (tid < 64) { hhv[tid] = 0.f; ccv[tid] = 0.f; }
    __syncthreads();
    int s0 = seg[0], s1 = seg[1];

    for (int it = 0; it < 3; ++it) {
        float g = b_ih[tid] + b_hh[tid];
        const float* wi = W_ih + tid * 128;
#pragma unroll 4
        for (int k = 0; k < 128; k++) g = fmaf(qs[k], wi[k], g);
        const float* wh = W_hh + tid * 64;
#pragma unroll 4
        for (int k = 0; k < 64; k++) g = fmaf(hhv[k], wh[k], g);
        gg[tid] = g;
        __syncthreads();
        if (tid < 64) {
            float ig = gg[tid], fg = gg[64 + tid], gv = gg[128 + tid], og = gg[192 + tid];
            float c = sigmoidf_(fg) * ccv[tid] + sigmoidf_(ig) * tanhf(gv);
            ccv[tid] = c;
            hhv[tid] = sigmoidf_(og) * tanhf(c);
        }
        __syncthreads();

        float q0 = hhv[lane], q1 = hhv[lane + 32];
        float wmax = -INFINITY;
        for (int i = s0 + wid; i < s1; i += 8) {
            const float* o = g_out + (size_t)i * 64;
            float v = o[lane] * q0 + o[lane + 32] * q1;
#pragma unroll
            for (int off = 16; off; off >>= 1) v += __shfl_xor_sync(0xffffffffu, v, off);
            wmax = fmaxf(wmax, v);
        }
        if (lane == 0) mw[wid] = wmax;
        __syncthreads();
        if (tid == 0) {
            float m = -INFINITY;
#pragma unroll
            for (int w = 0; w < 8; w++) m = fmaxf(m, mw[w]);
            mfin_s = m;
        }
        __syncthreads();
        float m = mfin_s;
        float r0a = 0.f, r1a = 0.f, sl = 0.f;
        for (int i = s0 + wid; i < s1; i += 8) {
            const float* o = g_out + (size_t)i * 64;
            float a0 = o[lane], a1 = o[lane + 32];
            float v = a0 * q0 + a1 * q1;
#pragma unroll
            for (int off = 16; off; off >>= 1) v += __shfl_xor_sync(0xffffffffu, v, off);
            float w = __expf(v - m);
            sl += w;
            r0a = fmaf(w, a0, r0a);
            r1a = fmaf(w, a1, r1a);
        }
        red[wid][lane] = r0a;
        red[wid][lane + 32] = r1a;
        if (lane == 0) sred[wid] = sl;
        __syncthreads();
        if (tid < 64) {
            float s = 0.f, r = 0.f;
#pragma unroll
            for (int w = 0; w < 8; w++) { s += sred[w]; r += red[w][tid]; }
            float inv = (s > 0.f) ? 1.0f / s : 0.f;
            qs[tid] = hhv[tid];
            qs[64 + tid] = r * inv;
        }
        __syncthreads();
    }

    if (tid < 64) {
        float z = b1[tid];
#pragma unroll 4
        for (int k = 0; k < 128; k++) z = fmaf(qs[k], W1[k * 64 + tid], z);
        gg[tid] = fmaxf(z, 0.f);
    }
    __syncthreads();
    if (tid < 32) {
        float p = gg[tid] * W2[tid] + gg[tid + 32] * W2[tid + 32];
#pragma unroll
        for (int off = 16; off; off >>= 1) p += __shfl_xor_sync(0xffffffffu, p, off);
        if (tid == 0) y[b] = p + b2[0];
    }
}

// ---------------- launch (single stream) ----------------
extern "C" void kernel_launch(void* const* d_in, const int* in_sizes, int n_in,
                              void* d_out, int out_size) {
    const float* x       = (const float*)d_in[0];
    const int*   ei      = (const int*)d_in[1];   // [2,E] int32
    const int*   batch   = (const int*)d_in[2];
    const float* W0      = (const float*)d_in[3];
    const float* b0      = (const float*)d_in[4];
    const float* Wg      = (const float*)d_in[5];
    const float* att_src = (const float*)d_in[6];
    const float* att_dst = (const float*)d_in[7];
    const float* bg      = (const float*)d_in[8];
    const float* Wh      = (const float*)d_in[9];
    const float* bh      = (const float*)d_in[10];
    const float* W_ih    = (const float*)d_in[11];
    const float* W_hh    = (const float*)d_in[12];
    const float* b_ih    = (const float*)d_in[13];
    const float* b_hh    = (const float*)d_in[14];
    const float* W1      = (const float*)d_in[15];
    const float* b1      = (const float*)d_in[16];
    const float* W2      = (const float*)d_in[17];
    const float* b2      = (const float*)d_in[18];
    float* y = (float*)d_out;

    k_h0<<<NN / 4, 256>>>(x, W0, b0);
    k_patt<<<1, 1024>>>(Wg, att_src, att_dst);
    k_att2<<<(NN * 16 + 255) / 256, 256>>>();
    k_xh<<<NN / 32, 256>>>(Wg);
    k_zero<<<(NN + 255) / 256, 256>>>();
    k_hist<<<(EE + 255) / 256, 256>>>(ei);
    k_scan<<<1, 1024>>>();
    k_scatter<<<(EE + 255) / 256, 256>>>(ei);
    k_agg<<<NN / 8, 256>>>(bg);
    k_out<<<(NN + 127) / 128, 256>>>(Wh, bh);
    k_s2s<<<BBATCH, 256>>>(batch, W_ih, W_hh, b_ih, b_hh, W1, b1, W2, b2, y);
}

// round 10
// speedup vs baseline: 1.9224x; 1.3450x over previous
#include <cuda_runtime.h>
#include <cuda_fp16.h>
#include <mma.h>
#include <math.h>

using namespace nvcuda;

#define NN   20000
#define NP   20096   // padded rows: 157*128, also /64
#define EE   320000
#define BBATCH 128
#define FIN  25
#define DIM  64
#define NH   8
#define F512 512   // NH*DIM

// ---------------- scratch (static device globals; zero-init, no allocation) ----
__device__ float   g_h0[NP * DIM];
__device__ __half  g_h0h[NP * DIM];
__device__ __half  g_Wgh[DIM * F512];
__device__ __half  g_Whh[F512 * DIM];
__device__ __half2 g_xh2[NP * (F512 / 2)];   // xh fp16
__device__ __half  g_aggh[NP * F512];        // agg fp16
__device__ float   g_P[DIM * 16];
__device__ float   g_as[NN * NH];
__device__ float   g_ad[NN * NH];
__device__ int     g_cnt[NN];
__device__ int     g_offs[NN + 1];
__device__ int     g_cursor[NN];
__device__ int     g_csr[EE];
__device__ float   g_out[NP * DIM];

__device__ __forceinline__ float lrelu(float x) { return x > 0.f ? x : 0.2f * x; }
__device__ __forceinline__ float sigmoidf_(float x) { return 1.f / (1.f + __expf(-x)); }

// ---------------- k1: h0 = relu(x @ W0 + b0); fp32 + fp16 copies ----------------
__global__ void k_h0(const float* __restrict__ x, const float* __restrict__ W0,
                     const float* __restrict__ b0) {
    __shared__ float sW[FIN * DIM];
    __shared__ float sb[DIM];
    __shared__ float sx[4][FIN];
    int tid = threadIdx.x;
    for (int i = tid; i < FIN * DIM; i += 256) sW[i] = W0[i];
    if (tid < DIM) sb[tid] = b0[tid];
    int rb = blockIdx.x * 4;
    if (tid < 4 * FIN) {
        int row = rb + tid / FIN;
        sx[tid / FIN][tid % FIN] = (row < NN) ? x[(size_t)row * FIN + tid % FIN] : 0.f;
    }
    __syncthreads();
    int c = tid & 63, r = tid >> 6;
    float acc = sb[c];
#pragma unroll
    for (int k = 0; k < FIN; k++) acc = fmaf(sx[r][k], sW[k * DIM + c], acc);
    float v = fmaxf(acc, 0.f);
    g_h0[(size_t)(rb + r) * DIM + c] = v;
    g_h0h[(size_t)(rb + r) * DIM + c] = __float2half(v);
}

// ---------------- weight conversion to fp16 (once per launch) ------------------
__global__ void k_cvtW(const float* __restrict__ Wg, const float* __restrict__ Wh) {
    int i = blockIdx.x * 256 + threadIdx.x;
    if (i < DIM * F512) g_Wgh[i] = __float2half(Wg[i]);
    if (i < F512 * DIM) g_Whh[i] = __float2half(Wh[i]);
}

// ---------------- k_patt: P[k][o] = sum_c Wg[k,64h+c]*att[h,c] (1 block) -------
__global__ void k_patt(const float* __restrict__ Wg, const float* __restrict__ as_,
                       const float* __restrict__ ad_) {
    int k = threadIdx.x >> 4, o = threadIdx.x & 15;
    int h = o & 7;
    const float* att = (o < 8) ? as_ : ad_;
    float s = 0.f;
#pragma unroll 8
    for (int c = 0; c < 64; c++)
        s = fmaf(Wg[k * F512 + h * 64 + c], att[h * 64 + c], s);
    g_P[k * 16 + o] = s;
}

// ---------------- k_att2: a_s/a_d = h0 @ P  (fp32 exact) -----------------------
__global__ void k_att2() {
    int idx = blockIdx.x * 256 + threadIdx.x;
    int n = idx >> 4, o = idx & 15;
    if (n >= NN) return;
    const float* h0r = g_h0 + (size_t)n * DIM;
    float s = 0.f;
#pragma unroll 8
    for (int k = 0; k < DIM; k++) s = fmaf(h0r[k], g_P[k * 16 + o], s);
    if (o < 8) g_as[n * 8 + o] = s;
    else       g_ad[n * 8 + (o - 8)] = s;
}

// ---------------- k_xh_mma: xh = h0h @ Wgh (fp16 HMMA, fp32 accum) -------------
// grid (NP/64, 4); block 256 (8 warps, 4x2); tile M=64,N=128,K=64 (one staging)
#define XA_LD 72
#define XB_LD 136
__global__ void __launch_bounds__(256) k_xh_mma() {
    __shared__ __align__(16) char smem[64 * 128 * 4];   // 32KB, phase-reused
    __half* sA = (__half*)smem;                          // 64 x XA_LD
    __half* sB = (__half*)(smem + 64 * XA_LD * 2);       // 64 x XB_LD
    float*  sC = (float*)smem;                           // 64 x 128

    int tid = threadIdx.x;
    int warp = tid >> 5;
    int rb = blockIdx.x * 64;
    int cb = blockIdx.y * 128;

    // stage A: 64 rows x 64 halves (8 int4/row)
    for (int i = tid; i < 512; i += 256) {
        int row = i >> 3, c8 = i & 7;
        *(int4*)&sA[row * XA_LD + c8 * 8] =
            *(const int4*)&g_h0h[(size_t)(rb + row) * DIM + c8 * 8];
    }
    // stage B: 64 rows x 128 halves (16 int4/row)
    for (int i = tid; i < 1024; i += 256) {
        int row = i >> 4, c8 = i & 15;
        *(int4*)&sB[row * XB_LD + c8 * 8] =
            *(const int4*)&g_Wgh[row * F512 + cb + c8 * 8];
    }
    __syncthreads();

    int wm = warp & 3, wn = warp >> 2;   // wm: 16-row group, wn: 64-col group
    wmma::fragment<wmma::accumulator, 16, 16, 16, float> acc[4];
#pragma unroll
    for (int n = 0; n < 4; n++) wmma::fill_fragment(acc[n], 0.f);

#pragma unroll
    for (int k = 0; k < 4; k++) {
        wmma::fragment<wmma::matrix_a, 16, 16, 16, __half, wmma::row_major> af;
        wmma::load_matrix_sync(af, &sA[(wm * 16) * XA_LD + k * 16], XA_LD);
#pragma unroll
        for (int n = 0; n < 4; n++) {
            wmma::fragment<wmma::matrix_b, 16, 16, 16, __half, wmma::row_major> bf;
            wmma::load_matrix_sync(bf, &sB[(k * 16) * XB_LD + wn * 64 + n * 16], XB_LD);
            wmma::mma_sync(acc[n], af, bf, acc[n]);
        }
    }
    __syncthreads();   // done reading sA/sB; reuse as sC
#pragma unroll
    for (int n = 0; n < 4; n++)
        wmma::store_matrix_sync(&sC[(wm * 16) * 128 + wn * 64 + n * 16], acc[n], 128,
                                wmma::mem_row_major);
    __syncthreads();

    // convert + write: 64 rows x 64 half2
    for (int i = tid; i < 64 * 64; i += 256) {
        int row = i >> 6, c2 = i & 63;
        float2 v = *(const float2*)&sC[row * 128 + 2 * c2];
        g_xh2[(size_t)(rb + row) * (F512 / 2) + (cb >> 1) + c2] = __floats2half2_rn(v.x, v.y);
    }
}

// ---------------- CSR build ----------------
__global__ void k_zero() {
    int i = blockIdx.x * 256 + threadIdx.x;
    if (i < NN) g_cnt[i] = 0;
}
__global__ void k_hist(const int* __restrict__ ei) {
    int e = blockIdx.x * 256 + threadIdx.x;
    if (e < EE) atomicAdd(&g_cnt[ei[EE + e]], 1);
}
__global__ void k_scan() {  // 1 block, 1024 threads
    __shared__ int partials[1024];
    int t = threadIdx.x;
    const int CH = 20;
    int base = t * CH;
    int local[CH];
    int s = 0;
#pragma unroll
    for (int u = 0; u < CH; u++) {
        int idx = base + u;
        int v = (idx < NN) ? g_cnt[idx] : 0;
        local[u] = s;
        s += v;
    }
    partials[t] = s;
    __syncthreads();
    for (int o = 1; o < 1024; o <<= 1) {
        int v = (t >= o) ? partials[t - o] : 0;
        __syncthreads();
        partials[t] += v;
        __syncthreads();
    }
    int pre = (t > 0) ? partials[t - 1] : 0;
#pragma unroll
    for (int u = 0; u < CH; u++) {
        int idx = base + u;
        if (idx < NN) {
            int o = pre + local[u];
            g_offs[idx] = o;
            g_cursor[idx] = o;
        }
    }
    if (t == 1023) g_offs[NN] = partials[1023];
}
__global__ void k_scatter(const int* __restrict__ ei) {
    int e = blockIdx.x * 256 + threadIdx.x;
    if (e < EE) {
        int d = ei[EE + e];
        int p = atomicAdd(&g_cursor[d], 1);
        g_csr[p] = ei[e];
    }
}

// ---------------- k4: GAT aggregation, warp per dst node (fp16 in/out) ---------
__global__ void __launch_bounds__(256) k_agg(const float* __restrict__ bg) {
    int n = (blockIdx.x * blockDim.x + threadIdx.x) >> 5;
    int lane = threadIdx.x & 31;
    if (n >= NN) return;
    int s0 = g_offs[n], s1 = g_offs[n + 1];
    int hh = lane & 7;
    float adh = g_ad[n * 8 + hh];

    // ---- pass 1: per-head max ----
    float m = -INFINITY;
    if (lane < 8) m = lrelu(g_as[n * 8 + lane] + adh);  // self-loop
    {
        int i = s0 + (lane >> 3);
        int src = (i < s1) ? g_csr[i] : -1;
        while (i < s1) {
            int inext = i + 4;
            int srcn = (inext < s1) ? g_csr[inext] : -1;
            float e = lrelu(g_as[src * 8 + hh] + adh);
            m = fmaxf(m, e);
            src = srcn;
            i = inext;
        }
    }
    m = fmaxf(m, __shfl_xor_sync(0xffffffffu, m, 8));
    m = fmaxf(m, __shfl_xor_sync(0xffffffffu, m, 16));

    // ---- pass 2: weighted accumulate ----
    float acc0[8], acc1[8];
#pragma unroll
    for (int t = 0; t < 8; t++) { acc0[t] = 0.f; acc1[t] = 0.f; }
    float ssum = 0.f;
    int head0 = lane >> 3;
    int head1 = (lane + 32) >> 3;
    int src_cur = n;
    for (int i = s0 - 1; i < s1; ++i) {
        int inext = i + 1;
        int src_next = (inext < s1) ? g_csr[inext] : 0;
        const int4* row = (const int4*)(g_xh2 + (size_t)src_cur * (F512 / 2));
        int4 v0 = row[lane];
        int4 v1 = row[lane + 32];
        float w = 0.f;
        if (lane < 8) {
            float e = lrelu(g_as[src_cur * 8 + lane] + adh);
            w = __expf(e - m);
            ssum += w;
        }
        float wj0 = __shfl_sync(0xffffffffu, w, head0);
        float wj1 = __shfl_sync(0xffffffffu, w, head1);
        const __half2* hp0 = (const __half2*)&v0;
        const __half2* hp1 = (const __half2*)&v1;
#pragma unroll
        for (int t = 0; t < 4; t++) {
            float2 f0 = __half22float2(hp0[t]);
            float2 f1 = __half22float2(hp1[t]);
            acc0[2 * t]     = fmaf(wj0, f0.x, acc0[2 * t]);
            acc0[2 * t + 1] = fmaf(wj0, f0.y, acc0[2 * t + 1]);
            acc1[2 * t]     = fmaf(wj1, f1.x, acc1[2 * t]);
            acc1[2 * t + 1] = fmaf(wj1, f1.y, acc1[2 * t + 1]);
        }
        src_cur = src_next;
    }

    float sj0 = __shfl_sync(0xffffffffu, ssum, head0);
    float sj1 = __shfl_sync(0xffffffffu, ssum, head1);
    float inv0 = 1.0f / sj0, inv1 = 1.0f / sj1;
    {
        int ch = 8 * lane;
        float4 b0 = __ldg((const float4*)&bg[ch]);
        float4 b1 = __ldg((const float4*)&bg[ch + 4]);
        __half2 o[4];
        o[0] = __floats2half2_rn(fmaxf(acc0[0] * inv0 + b0.x, 0.f), fmaxf(acc0[1] * inv0 + b0.y, 0.f));
        o[1] = __floats2half2_rn(fmaxf(acc0[2] * inv0 + b0.z, 0.f), fmaxf(acc0[3] * inv0 + b0.w, 0.f));
        o[2] = __floats2half2_rn(fmaxf(acc0[4] * inv0 + b1.x, 0.f), fmaxf(acc0[5] * inv0 + b1.y, 0.f));
        o[3] = __floats2half2_rn(fmaxf(acc0[6] * inv0 + b1.z, 0.f), fmaxf(acc0[7] * inv0 + b1.w, 0.f));
        *(int4*)&g_aggh[(size_t)n * F512 + ch] = *(int4*)o;
    }
    {
        int ch = 8 * (lane + 32);
        float4 b0 = __ldg((const float4*)&bg[ch]);
        float4 b1 = __ldg((const float4*)&bg[ch + 4]);
        __half2 o[4];
        o[0] = __floats2half2_rn(fmaxf(acc1[0] * inv1 + b0.x, 0.f), fmaxf(acc1[1] * inv1 + b0.y, 0.f));
        o[1] = __floats2half2_rn(fmaxf(acc1[2] * inv1 + b0.z, 0.f), fmaxf(acc1[3] * inv1 + b0.w, 0.f));
        o[2] = __floats2half2_rn(fmaxf(acc1[4] * inv1 + b1.x, 0.f), fmaxf(acc1[5] * inv1 + b1.y, 0.f));
        o[3] = __floats2half2_rn(fmaxf(acc1[6] * inv1 + b1.z, 0.f), fmaxf(acc1[7] * inv1 + b1.w, 0.f));
        *(int4*)&g_aggh[(size_t)n * F512 + ch] = *(int4*)o;
    }
}

// ---------------- k_out_mma: out = relu(aggh @ Whh + bh) (HMMA) ----------------
// grid 157; block 256 (8 warps); tile M=128,N=64; K=512 in 8 chunks of 64
#define OA_LD 72
#define OB_LD 72
__global__ void __launch_bounds__(256) k_out_mma(const float* __restrict__ bh) {
    __shared__ __align__(16) char smem[128 * 64 * 4];   // 32KB phase-reused
    __half* sA = (__half*)smem;                          // 128 x OA_LD
    __half* sB = (__half*)(smem + 128 * OA_LD * 2);      // 64 x OB_LD
    float*  sC = (float*)smem;                           // 128 x 64

    int tid = threadIdx.x;
    int warp = tid >> 5;
    int rb = blockIdx.x * 128;

    wmma::fragment<wmma::accumulator, 16, 16, 16, float> acc[4];
#pragma unroll
    for (int n = 0; n < 4; n++) wmma::fill_fragment(acc[n], 0.f);

    for (int kc = 0; kc < 8; kc++) {
        // stage A: 128 rows x 64 halves (8 int4/row)
        for (int i = tid; i < 1024; i += 256) {
            int row = i >> 3, c8 = i & 7;
            *(int4*)&sA[row * OA_LD + c8 * 8] =
                *(const int4*)&g_aggh[(size_t)(rb + row) * F512 + kc * 64 + c8 * 8];
        }
        // stage B: 64 rows x 64 halves
        for (int i = tid; i < 512; i += 256) {
            int row = i >> 3, c8 = i & 7;
            *(int4*)&sB[row * OB_LD + c8 * 8] =
                *(const int4*)&g_Whh[(kc * 64 + row) * DIM + c8 * 8];
        }
        __syncthreads();
#pragma unroll
        for (int k = 0; k < 4; k++) {
            wmma::fragment<wmma::matrix_a, 16, 16, 16, __half, wmma::row_major> af;
            wmma::load_matrix_sync(af, &sA[(warp * 16) * OA_LD + k * 16], OA_LD);
#pragma unroll
            for (int n = 0; n < 4; n++) {
                wmma::fragment<wmma::matrix_b, 16, 16, 16, __half, wmma::row_major> bf;
                wmma::load_matrix_sync(bf, &sB[(k * 16) * OB_LD + n * 16], OB_LD);
                wmma::mma_sync(acc[n], af, bf, acc[n]);
            }
        }
        __syncthreads();
    }
#pragma unroll
    for (int n = 0; n < 4; n++)
        wmma::store_matrix_sync(&sC[(warp * 16) * 64 + n * 16], acc[n], 64,
                                wmma::mem_row_major);
    __syncthreads();

    // epilogue: bias + relu, write fp32 out (128 rows x 16 float4)
    for (int i = tid; i < 128 * 16; i += 256) {
        int row = i >> 4, c4 = i & 15;
        float4 v = *(const float4*)&sC[row * 64 + c4 * 4];
        float4 b = __ldg((const float4*)&bh[c4 * 4]);
        v.x = fmaxf(v.x + b.x, 0.f);
        v.y = fmaxf(v.y + b.y, 0.f);
        v.z = fmaxf(v.z + b.z, 0.f);
        v.w = fmaxf(v.w + b.w, 0.f);
        *(float4*)&g_out[(size_t)(rb + row) * DIM + c4 * 4] = v;
    }
}

// ---------------- k6: Set2Set (3 steps) + final MLP; one block per graph -------
__global__ void __launch_bounds__(256) k_s2s(
    const int* __restrict__ batch, const float* __restrict__ W_ih,
    const float* __restrict__ W_hh, const float* __restrict__ b_ih,
    const float* __restrict__ b_hh, const float* __restrict__ W1,
    const float* __restrict__ b1, const float* __restrict__ W2,
    const float* __restrict__ b2, float* __restrict__ y) {
    int b = blockIdx.x;
    int tid = threadIdx.x, lane = tid & 31, wid = tid >> 5;
    __shared__ float qs[128], hhv[64], ccv[64], gg[256];
    __shared__ float red[8][64];
    __shared__ float sred[8], mw[8];
    __shared__ float mfin_s;
    __shared__ int seg[2];
    if (tid == 0) {
        int lo = 0, hi = NN;
        while (lo < hi) { int mid = (lo + hi) >> 1; if (batch[mid] < b) lo = mid + 1; else hi = mid; }
        seg[0] = lo;
        hi = NN;
        while (lo < hi) { int mid = (lo + hi) >> 1; if (batch[mid] < b + 1) lo = mid + 1; else hi = mid; }
        seg[1] = lo;
    }
    if (tid < 128) qs[tid] = 0.f;
    if (tid < 64) { hhv[tid] = 0.f; ccv[tid] = 0.f; }
    __syncthreads();
    int s0 = seg[0], s1 = seg[1];

    for (int it = 0; it < 3; ++it) {
        float g = b_ih[tid] + b_hh[tid];
        const float* wi = W_ih + tid * 128;
#pragma unroll 4
        for (int k = 0; k < 128; k++) g = fmaf(qs[k], wi[k], g);
        const float* wh = W_hh + tid * 64;
#pragma unroll 4
        for (int k = 0; k < 64; k++) g = fmaf(hhv[k], wh[k], g);
        gg[tid] = g;
        __syncthreads();
        if (tid < 64) {
            float ig = gg[tid], fg = gg[64 + tid], gv = gg[128 + tid], og = gg[192 + tid];
            float c = sigmoidf_(fg) * ccv[tid] + sigmoidf_(ig) * tanhf(gv);
            ccv[tid] = c;
            hhv[tid] = sigmoidf_(og) * tanhf(c);
        }
        __syncthreads();

        float q0 = hhv[lane], q1 = hhv[lane + 32];
        float wmax = -INFINITY;
        for (int i = s0 + wid; i < s1; i += 8) {
            const float* o = g_out + (size_t)i * 64;
            float v = o[lane] * q0 + o[lane + 32] * q1;
#pragma unroll
            for (int off = 16; off; off >>= 1) v += __shfl_xor_sync(0xffffffffu, v, off);
            wmax = fmaxf(wmax, v);
        }
        if (lane == 0) mw[wid] = wmax;
        __syncthreads();
        if (tid == 0) {
            float m = -INFINITY;
#pragma unroll
            for (int w = 0; w < 8; w++) m = fmaxf(m, mw[w]);
            mfin_s = m;
        }
        __syncthreads();
        float m = mfin_s;
        float r0a = 0.f, r1a = 0.f, sl = 0.f;
        for (int i = s0 + wid; i < s1; i += 8) {
            const float* o = g_out + (size_t)i * 64;
            float a0 = o[lane], a1 = o[lane + 32];
            float v = a0 * q0 + a1 * q1;
#pragma unroll
            for (int off = 16; off; off >>= 1) v += __shfl_xor_sync(0xffffffffu, v, off);
            float w = __expf(v - m);
            sl += w;
            r0a = fmaf(w, a0, r0a);
            r1a = fmaf(w, a1, r1a);
        }
        red[wid][lane] = r0a;
        red[wid][lane + 32] = r1a;
        if (lane == 0) sred[wid] = sl;
        __syncthreads();
        if (tid < 64) {
            float s = 0.f, r = 0.f;
#pragma unroll
            for (int w = 0; w < 8; w++) { s += sred[w]; r += red[w][tid]; }
            float inv = (s > 0.f) ? 1.0f / s : 0.f;
            qs[tid] = hhv[tid];
            qs[64 + tid] = r * inv;
        }
        __syncthreads();
    }

    if (tid < 64) {
        float z = b1[tid];
#pragma unroll 4
        for (int k = 0; k < 128; k++) z = fmaf(qs[k], W1[k * 64 + tid], z);
        gg[tid] = fmaxf(z, 0.f);
    }
    __syncthreads();
    if (tid < 32) {
        float p = gg[tid] * W2[tid] + gg[tid + 32] * W2[tid + 32];
#pragma unroll
        for (int off = 16; off; off >>= 1) p += __shfl_xor_sync(0xffffffffu, p, off);
        if (tid == 0) y[b] = p + b2[0];
    }
}

// ---------------- launch (single stream) ----------------
extern "C" void kernel_launch(void* const* d_in, const int* in_sizes, int n_in,
                              void* d_out, int out_size) {
    const float* x       = (const float*)d_in[0];
    const int*   ei      = (const int*)d_in[1];   // [2,E] int32
    const int*   batch   = (const int*)d_in[2];
    const float* W0      = (const float*)d_in[3];
    const float* b0      = (const float*)d_in[4];
    const float* Wg      = (const float*)d_in[5];
    const float* att_src = (const float*)d_in[6];
    const float* att_dst = (const float*)d_in[7];
    const float* bg      = (const float*)d_in[8];
    const float* Wh      = (const float*)d_in[9];
    const float* bh      = (const float*)d_in[10];
    const float* W_ih    = (const float*)d_in[11];
    const float* W_hh    = (const float*)d_in[12];
    const float* b_ih    = (const float*)d_in[13];
    const float* b_hh    = (const float*)d_in[14];
    const float* W1      = (const float*)d_in[15];
    const float* b1      = (const float*)d_in[16];
    const float* W2      = (const float*)d_in[17];
    const float* b2      = (const float*)d_in[18];
    float* y = (float*)d_out;

    k_h0<<<NP / 4, 256>>>(x, W0, b0);
    k_cvtW<<<(DIM * F512 + 255) / 256, 256>>>(Wg, Wh);
    k_patt<<<1, 1024>>>(Wg, att_src, att_dst);
    k_att2<<<(NN * 16 + 255) / 256, 256>>>();
    k_xh_mma<<<dim3(NP / 64, 4), 256>>>();
    k_zero<<<(NN + 255) / 256, 256>>>();
    k_hist<<<(EE + 255) / 256, 256>>>(ei);
    k_scan<<<1, 1024>>>();
    k_scatter<<<(EE + 255) / 256, 256>>>(ei);
    k_agg<<<NN / 8, 256>>>(bg);
    k_out_mma<<<NP / 128, 256>>>(bh);
    k_s2s<<<BBATCH, 256>>>(batch, W_ih, W_hh, b_ih, b_hh, W1, b1, W2, b2, y);
}